// round 2
// baseline (speedup 1.0000x reference)
#include <cuda_runtime.h>
#include <math.h>

// Problem shape (fixed by the dataset)
#define Bc 8
#define Dc 128
#define Nc 4096           // 64*64
#define TEMP_INV 10.0f    // 1 / 0.1

// Scratch (allocation-free rule: __device__ globals)
__device__ float g_norm[Bc * Nc * Dc];     // normalized features, (B, N, D) contiguous-D
__device__ float g_partial[65536];         // per-block partial loss sums

// ---------------------------------------------------------------------------
// Kernel 1: L2-normalize over D and transpose (B,D,N) -> (B,N,D).
// Block = 256 threads handles a 128(d) x 32(n) tile of one batch b.
// Both the global read (along n) and global write (along d) are coalesced;
// the transpose happens in shared memory with a +1-style pad (33) to avoid
// bank conflicts.
// ---------------------------------------------------------------------------
__global__ void normalize_kernel(const float* __restrict__ in) {
    __shared__ float tile[Dc][33];
    __shared__ float psum[8][32];
    __shared__ float sinv[32];

    const int b      = blockIdx.y;
    const int n_base = blockIdx.x * 32;
    const int t      = threadIdx.x;

    const float* src = in + (size_t)b * Dc * Nc + n_base;

    // Load tile: consecutive threads -> consecutive n -> 128B coalesced
    #pragma unroll
    for (int k = t; k < Dc * 32; k += 256) {
        int d  = k >> 5;
        int n0 = k & 31;
        tile[d][n0] = src[(size_t)d * Nc + n0];
    }
    __syncthreads();

    // Partial sum of squares: 8 chunks of 16 d-values per column
    {
        int n0 = t & 31, chunk = t >> 5;
        float s = 0.f;
        #pragma unroll
        for (int dd = 0; dd < 16; dd++) {
            float v = tile[chunk * 16 + dd][n0];
            s += v * v;
        }
        psum[chunk][n0] = s;
    }
    __syncthreads();

    if (t < 32) {
        float s = 0.f;
        #pragma unroll
        for (int c = 0; c < 8; c++) s += psum[c][t];
        float nrm = sqrtf(s);
        sinv[t] = 1.0f / fmaxf(nrm, 1e-12f);   // matches F.normalize eps
    }
    __syncthreads();

    // Write transposed: warp w writes whole vectors (contiguous in d)
    const int wid = t >> 5, lane = t & 31;
    for (int n0 = wid; n0 < 32; n0 += 8) {
        float inv  = sinv[n0];
        float* dst = g_norm + ((size_t)(b * Nc + n_base + n0)) * Dc;
        #pragma unroll
        for (int k = 0; k < 4; k++) {
            int d = lane + 32 * k;
            dst[d] = tile[d][n0] * inv;
        }
    }
}

// ---------------------------------------------------------------------------
// Kernel 2: one warp per (pos or neg) pair. Each lane loads a float4 from
// each 128-float vector (contiguous 512B, L2-resident), butterfly-reduces
// the dot product, applies -log_sigmoid. Block writes one partial sum.
// ---------------------------------------------------------------------------
__global__ void gather_kernel(const int* __restrict__ pb, const int* __restrict__ pi,
                              const int* __restrict__ pj, const int* __restrict__ nb,
                              const int* __restrict__ ni, const int* __restrict__ nj,
                              int P) {
    const int gw   = (blockIdx.x * blockDim.x + threadIdx.x) >> 5;
    const int lane = threadIdx.x & 31;

    float val = 0.f;
    if (gw < 2 * P) {
        const bool neg = (gw >= P);
        const int p = neg ? gw - P : gw;
        const int b = neg ? nb[p] : pb[p];
        const int i = neg ? ni[p] : pi[p];
        const int j = neg ? nj[p] : pj[p];

        const float4* vi = (const float4*)(g_norm + ((size_t)(b * Nc + i)) * Dc);
        const float4* vj = (const float4*)(g_norm + ((size_t)(b * Nc + j)) * Dc);
        float4 a = vi[lane];
        float4 c = vj[lane];
        float dot = a.x * c.x + a.y * c.y + a.z * c.z + a.w * c.w;
        #pragma unroll
        for (int off = 16; off; off >>= 1)
            dot += __shfl_xor_sync(0xffffffffu, dot, off);

        if (lane == 0) {
            float s = dot * TEMP_INV;
            // pos: softplus(-s); neg: softplus(+s)   (stable form)
            float x = neg ? s : -s;
            val = fmaxf(x, 0.f) + log1pf(expf(-fabsf(x)));
        }
    }

    __shared__ float sred[8];
    if (lane == 0) sred[threadIdx.x >> 5] = val;
    __syncthreads();
    if (threadIdx.x == 0) {
        float s = 0.f;
        #pragma unroll
        for (int w = 0; w < 8; w++) s += sred[w];
        g_partial[blockIdx.x] = s;
    }
}

// ---------------------------------------------------------------------------
// Kernel 3: deterministic final reduction (fixed strided order + tree).
// No float atomics anywhere -> bit-identical across graph replays.
// ---------------------------------------------------------------------------
__global__ void finalize_kernel(int nblocks, int P, float* __restrict__ out) {
    __shared__ float sred[256];
    float s = 0.f;
    for (int k = threadIdx.x; k < nblocks; k += 256) s += g_partial[k];
    sred[threadIdx.x] = s;
    __syncthreads();
    #pragma unroll
    for (int stride = 128; stride; stride >>= 1) {
        if (threadIdx.x < stride) sred[threadIdx.x] += sred[threadIdx.x + stride];
        __syncthreads();
    }
    if (threadIdx.x == 0) out[0] = sred[0] / (float)P;
}

extern "C" void kernel_launch(void* const* d_in, const int* in_sizes, int n_in,
                              void* d_out, int out_size) {
    const float* feats = (const float*)d_in[0];
    const int*   pb    = (const int*)d_in[1];
    const int*   pi    = (const int*)d_in[2];
    const int*   pj    = (const int*)d_in[3];
    const int*   nb    = (const int*)d_in[4];
    const int*   ni    = (const int*)d_in[5];
    const int*   nj    = (const int*)d_in[6];
    const int    P     = in_sizes[1];

    normalize_kernel<<<dim3(Nc / 32, Bc), 256>>>(feats);

    const int warps   = 2 * P;                 // one warp per pair (pos then neg)
    const int nblocks = (warps + 7) / 8;       // 8 warps / block
    gather_kernel<<<nblocks, 256>>>(pb, pi, pj, nb, ni, nj, P);

    finalize_kernel<<<1, 256>>>(nblocks, P, (float*)d_out);
}

// round 3
// speedup vs baseline: 1.0236x; 1.0236x over previous
#include <cuda_runtime.h>
#include <cuda_fp16.h>
#include <math.h>

// Problem shape (fixed by the dataset)
#define Bc 8
#define Dc 128
#define Nc 4096           // 64*64
#define TEMP_INV 10.0f    // 1 / 0.1
#define TN 64             // n-tile width in normalize

// Scratch (allocation-free rule: __device__ globals).
// Normalized features stored fp16, (B, N, D) with D contiguous: 256 B/vector.
__device__ uint4 g_norm4[Bc * Nc * Dc * 2 / 16];   // 8.4 MB, 16B-aligned
__device__ float g_partial[16384];                 // per-block partial loss sums

// ---------------------------------------------------------------------------
// Kernel 1: L2-normalize over D and transpose (B,D,N) -> (B,N,D), fp16 out.
// Block = 256 threads handles a 128(d) x 64(n) tile of one batch b.
// float4 global loads (8 per thread, batched -> high MLP); smem transpose
// with 65-float row pad (conflict-free column reads for the reduction,
// 2-way on the write-phase read).
// ---------------------------------------------------------------------------
__global__ void normalize_kernel(const float* __restrict__ in) {
    __shared__ float tile[Dc][65];
    __shared__ float psum[4][TN];
    __shared__ float sinv[TN];

    const int b      = blockIdx.y;
    const int n_base = blockIdx.x * TN;
    const int t      = threadIdx.x;

    const float4* src = (const float4*)(in + (size_t)b * Dc * Nc + n_base);

    // Load tile: 2048 float4; thread t takes f = t + 256k. 16 float4 per d-row,
    // warp covers 2 contiguous 256B rows -> fully coalesced.
    #pragma unroll
    for (int k = 0; k < 8; k++) {
        int f = t + 256 * k;
        int d = f >> 4;
        int q = f & 15;
        float4 v = src[(size_t)d * (Nc / 4) + q];
        int n0 = q * 4;
        tile[d][n0]     = v.x;
        tile[d][n0 + 1] = v.y;
        tile[d][n0 + 2] = v.z;
        tile[d][n0 + 3] = v.w;
    }
    __syncthreads();

    // Sum of squares: thread owns column n0, chunk of 32 d-values.
    {
        int n0 = t & 63, c = t >> 6;
        float s = 0.f;
        #pragma unroll
        for (int dd = 0; dd < 32; dd++) {
            float v = tile[c * 32 + dd][n0];
            s += v * v;
        }
        psum[c][n0] = s;
    }
    __syncthreads();

    if (t < TN) {
        float s = psum[0][t] + psum[1][t] + psum[2][t] + psum[3][t];
        sinv[t] = 1.0f / fmaxf(sqrtf(s), 1e-12f);   // matches F.normalize eps
    }
    __syncthreads();

    // Write fp16 vectors: warp w writes vectors n0 = w, w+8, ...; lane covers
    // half2 slots lane and lane+32 (two 128B coalesced stores per vector).
    const int wid = t >> 5, lane = t & 31;
    for (int n0 = wid; n0 < TN; n0 += 8) {
        float inv = sinv[n0];
        __half2* dst = ((__half2*)g_norm4) + ((size_t)(b * Nc + n_base + n0)) * 64;
        #pragma unroll
        for (int k = 0; k < 2; k++) {
            int d = 2 * (lane + 32 * k);
            float2 v = make_float2(tile[d][n0] * inv, tile[d + 1][n0] * inv);
            dst[lane + 32 * k] = __float22half2_rn(v);
        }
    }
}

// ---------------------------------------------------------------------------
// Kernel 2: one warp per pair. Each lane loads one uint2 (4 halves) of each
// 256B vector (L2-resident), fp32 dot, butterfly reduce, -log_sigmoid.
// 512-thread blocks -> 16 pairs/block.
// ---------------------------------------------------------------------------
__global__ void gather_kernel(const int* __restrict__ pb, const int* __restrict__ pi,
                              const int* __restrict__ pj, const int* __restrict__ nb,
                              const int* __restrict__ ni, const int* __restrict__ nj,
                              int P) {
    const int gw   = (blockIdx.x * blockDim.x + threadIdx.x) >> 5;
    const int lane = threadIdx.x & 31;

    float val = 0.f;
    if (gw < 2 * P) {
        const bool neg = (gw >= P);
        const int p = neg ? gw - P : gw;
        const int b = neg ? nb[p] : pb[p];
        const int i = neg ? ni[p] : pi[p];
        const int j = neg ? nj[p] : pj[p];

        const uint2* vi = (const uint2*)g_norm4 + ((size_t)(b * Nc + i)) * 32;
        const uint2* vj = (const uint2*)g_norm4 + ((size_t)(b * Nc + j)) * 32;
        uint2 ua = vi[lane];
        uint2 ub = vj[lane];
        float2 a0 = __half22float2(*(const __half2*)&ua.x);
        float2 a1 = __half22float2(*(const __half2*)&ua.y);
        float2 c0 = __half22float2(*(const __half2*)&ub.x);
        float2 c1 = __half22float2(*(const __half2*)&ub.y);
        float dot = a0.x * c0.x + a0.y * c0.y + a1.x * c1.x + a1.y * c1.y;

        #pragma unroll
        for (int off = 16; off; off >>= 1)
            dot += __shfl_xor_sync(0xffffffffu, dot, off);

        if (lane == 0) {
            float s = dot * TEMP_INV;
            // pos: softplus(-s); neg: softplus(+s)   (stable form)
            float x = neg ? s : -s;
            val = fmaxf(x, 0.f) + log1pf(expf(-fabsf(x)));
        }
    }

    __shared__ float sred[16];
    if (lane == 0) sred[threadIdx.x >> 5] = val;
    __syncthreads();
    if (threadIdx.x == 0) {
        float s = 0.f;
        #pragma unroll
        for (int w = 0; w < 16; w++) s += sred[w];
        g_partial[blockIdx.x] = s;
    }
}

// ---------------------------------------------------------------------------
// Kernel 3: deterministic final reduction (fixed strided order + tree).
// ---------------------------------------------------------------------------
__global__ void finalize_kernel(int nblocks, int P, float* __restrict__ out) {
    __shared__ float sred[256];
    float s = 0.f;
    for (int k = threadIdx.x; k < nblocks; k += 256) s += g_partial[k];
    sred[threadIdx.x] = s;
    __syncthreads();
    #pragma unroll
    for (int stride = 128; stride; stride >>= 1) {
        if (threadIdx.x < stride) sred[threadIdx.x] += sred[threadIdx.x + stride];
        __syncthreads();
    }
    if (threadIdx.x == 0) out[0] = sred[0] / (float)P;
}

extern "C" void kernel_launch(void* const* d_in, const int* in_sizes, int n_in,
                              void* d_out, int out_size) {
    const float* feats = (const float*)d_in[0];
    const int*   pb    = (const int*)d_in[1];
    const int*   pi    = (const int*)d_in[2];
    const int*   pj    = (const int*)d_in[3];
    const int*   nb    = (const int*)d_in[4];
    const int*   ni    = (const int*)d_in[5];
    const int*   nj    = (const int*)d_in[6];
    const int    P     = in_sizes[1];

    normalize_kernel<<<dim3(Nc / TN, Bc), 256>>>(feats);

    const int warps   = 2 * P;                  // one warp per pair
    const int nblocks = (warps + 15) / 16;      // 16 warps / block
    gather_kernel<<<nblocks, 512>>>(pb, pi, pj, nb, ni, nj, P);

    finalize_kernel<<<1, 256>>>(nblocks, P, (float*)d_out);
}

// round 5
// speedup vs baseline: 1.1769x; 1.1498x over previous
#include <cuda_runtime.h>
#include <cuda_fp16.h>
#include <math.h>

// Problem shape (fixed by the dataset)
#define Bc 8
#define Dc 128
#define Nc 4096           // 64*64
#define TEMP_INV 10.0f    // 1 / 0.1
#define TN 32             // n-tile width in normalize

// Scratch (allocation-free rule: __device__ globals).
// Normalized features stored fp16, (B, N, D) with D contiguous: 256 B/vector.
__device__ uint4 g_norm4[Bc * Nc * Dc * 2 / 16];   // 8.4 MB, 16B-aligned
__device__ float g_partial[16384];                 // per-block partial loss sums

// ---------------------------------------------------------------------------
// Kernel 1: L2-normalize over D and transpose (B,D,N) -> (B,N,D), fp16 out.
// Block = 256 threads handles a 128(d) x 32(n) tile of one batch b.
// 1024 blocks (good wave granularity / occupancy) AND float4 loads
// (4 per thread, front-batched -> MLP) -- rounds 1/2 each had only one
// of these and both stalled at 9.4us.
// ---------------------------------------------------------------------------
__global__ void normalize_kernel(const float* __restrict__ in) {
    __shared__ float tile[Dc][33];
    __shared__ float psum[8][TN];
    __shared__ float sinv[TN];

    const int b      = blockIdx.y;
    const int n_base = blockIdx.x * TN;
    const int t      = threadIdx.x;

    const float4* src = (const float4*)(in + (size_t)b * Dc * Nc + n_base);

    // Load tile: 1024 float4 (8 per d-row); warp covers 4 contiguous 128B rows.
    float4 v[4];
    #pragma unroll
    for (int k = 0; k < 4; k++) {
        int f = t + 256 * k;
        int d = f >> 3;
        int q = f & 7;
        v[k] = src[(size_t)d * (Nc / 4) + q];
    }
    #pragma unroll
    for (int k = 0; k < 4; k++) {
        int f = t + 256 * k;
        int d = f >> 3;
        int n0 = (f & 7) * 4;
        tile[d][n0]     = v[k].x;
        tile[d][n0 + 1] = v[k].y;
        tile[d][n0 + 2] = v[k].z;
        tile[d][n0 + 3] = v[k].w;
    }
    __syncthreads();

    // Sum of squares: thread owns column n0, chunk of 16 d-values.
    {
        int n0 = t & 31, c = t >> 5;
        float s = 0.f;
        #pragma unroll
        for (int dd = 0; dd < 16; dd++) {
            float x = tile[c * 16 + dd][n0];
            s += x * x;
        }
        psum[c][n0] = s;
    }
    __syncthreads();

    if (t < TN) {
        float s = 0.f;
        #pragma unroll
        for (int c = 0; c < 8; c++) s += psum[c][t];
        sinv[t] = 1.0f / fmaxf(sqrtf(s), 1e-12f);   // matches F.normalize eps
    }
    __syncthreads();

    // Write fp16 vectors: warp w writes vectors n0 = w, w+8, ...; lane covers
    // half2 slots lane and lane+32 (two 128B coalesced stores per vector).
    const int wid = t >> 5, lane = t & 31;
    #pragma unroll
    for (int n0i = 0; n0i < 4; n0i++) {
        int n0 = wid + 8 * n0i;
        float inv = sinv[n0];
        __half2* dst = ((__half2*)g_norm4) + ((size_t)(b * Nc + n_base + n0)) * 64;
        #pragma unroll
        for (int k = 0; k < 2; k++) {
            int d = 2 * (lane + 32 * k);
            float2 f2 = make_float2(tile[d][n0] * inv, tile[d + 1][n0] * inv);
            dst[lane + 32 * k] = __float22half2_rn(f2);
        }
    }
}

// ---------------------------------------------------------------------------
// Kernel 2: one warp handles pair g for BOTH pos and neg lists: 4 independent
// 8B loads per lane (4 vectors, L2-resident), two interleaved fp32 dots +
// butterfly reductions, one combined softplus pair on lane0.
// 512-thread blocks -> 16 pairs/block -> P/16 blocks.
// ---------------------------------------------------------------------------
__global__ void gather_kernel(const int* __restrict__ pb, const int* __restrict__ pi,
                              const int* __restrict__ pj, const int* __restrict__ nb,
                              const int* __restrict__ ni, const int* __restrict__ nj,
                              int P) {
    const int gw   = (blockIdx.x * blockDim.x + threadIdx.x) >> 5;
    const int lane = threadIdx.x & 31;

    float val = 0.f;
    if (gw < P) {
        const int b1 = pb[gw], i1 = pi[gw], j1 = pj[gw];
        const int b2 = nb[gw], i2 = ni[gw], j2 = nj[gw];

        const uint2* base = (const uint2*)g_norm4;
        uint2 ua = base[((size_t)(b1 * Nc + i1)) * 32 + lane];
        uint2 ub = base[((size_t)(b1 * Nc + j1)) * 32 + lane];
        uint2 uc = base[((size_t)(b2 * Nc + i2)) * 32 + lane];
        uint2 ud = base[((size_t)(b2 * Nc + j2)) * 32 + lane];

        float2 a0 = __half22float2(*(const __half2*)&ua.x);
        float2 a1 = __half22float2(*(const __half2*)&ua.y);
        float2 b0 = __half22float2(*(const __half2*)&ub.x);
        float2 b1f = __half22float2(*(const __half2*)&ub.y);
        float2 c0 = __half22float2(*(const __half2*)&uc.x);
        float2 c1 = __half22float2(*(const __half2*)&uc.y);
        float2 d0 = __half22float2(*(const __half2*)&ud.x);
        float2 d1 = __half22float2(*(const __half2*)&ud.y);

        float dp = a0.x * b0.x + a0.y * b0.y + a1.x * b1f.x + a1.y * b1f.y;
        float dn = c0.x * d0.x + c0.y * d0.y + c1.x * d1.x + c1.y * d1.y;

        #pragma unroll
        for (int off = 16; off; off >>= 1) {
            dp += __shfl_xor_sync(0xffffffffu, dp, off);
            dn += __shfl_xor_sync(0xffffffffu, dn, off);
        }

        if (lane == 0) {
            float xp = -dp * TEMP_INV;   // softplus(-s_pos)
            float xn =  dn * TEMP_INV;   // softplus(+s_neg)
            val  = fmaxf(xp, 0.f) + log1pf(expf(-fabsf(xp)));
            val += fmaxf(xn, 0.f) + log1pf(expf(-fabsf(xn)));
        }
    }

    __shared__ float sred[16];
    if (lane == 0) sred[threadIdx.x >> 5] = val;
    __syncthreads();
    if (threadIdx.x == 0) {
        float s = 0.f;
        #pragma unroll
        for (int w = 0; w < 16; w++) s += sred[w];
        g_partial[blockIdx.x] = s;
    }
}

// ---------------------------------------------------------------------------
// Kernel 3: deterministic final reduction. 1024 threads -> only
// ceil(nblocks/1024) independent loads per thread, then smem tree.
// ---------------------------------------------------------------------------
__global__ void finalize_kernel(int nblocks, int P, float* __restrict__ out) {
    __shared__ float sred[1024];
    float s = 0.f;
    for (int k = threadIdx.x; k < nblocks; k += 1024) s += g_partial[k];
    sred[threadIdx.x] = s;
    __syncthreads();
    #pragma unroll
    for (int stride = 512; stride; stride >>= 1) {
        if (threadIdx.x < stride) sred[threadIdx.x] += sred[threadIdx.x + stride];
        __syncthreads();
    }
    if (threadIdx.x == 0) out[0] = sred[0] / (float)P;
}

extern "C" void kernel_launch(void* const* d_in, const int* in_sizes, int n_in,
                              void* d_out, int out_size) {
    const float* feats = (const float*)d_in[0];
    const int*   pb    = (const int*)d_in[1];
    const int*   pi    = (const int*)d_in[2];
    const int*   pj    = (const int*)d_in[3];
    const int*   nb    = (const int*)d_in[4];
    const int*   ni    = (const int*)d_in[5];
    const int*   nj    = (const int*)d_in[6];
    const int    P     = in_sizes[1];

    normalize_kernel<<<dim3(Nc / TN, Bc), 256>>>(feats);

    const int nblocks = (P + 15) / 16;          // one warp per (pos,neg) pair-index
    gather_kernel<<<nblocks, 512>>>(pb, pi, pj, nb, ni, nj, P);

    finalize_kernel<<<1, 1024>>>(nblocks, P, (float*)d_out);
}

// round 7
// speedup vs baseline: 1.5213x; 1.2927x over previous
#include <cuda_runtime.h>
#include <cuda_fp16.h>
#include <math.h>

// Problem shape (fixed by the dataset)
#define Bc 8
#define Dc 128
#define Nc 4096           // 64*64
#define TEMP_INV 10.0f    // 1 / 0.1
#define TN 32             // n-tile width in normalize

// Scratch (allocation-free rule: __device__ globals).
// Normalized features stored fp16, (B, N, D) with D contiguous: 256 B/vector.
__device__ uint4 g_norm4[Bc * Nc * Dc * 2 / 16];   // 8.4 MB, 16B-aligned
__device__ float g_partial[16384];                 // per-block partial loss sums

// ---------------------------------------------------------------------------
// Kernel 1: L2-normalize over D and transpose (B,D,N) -> (B,N,D), fp16 out.
// (unchanged from round 5: 1024 blocks + float4 loads, 8.3us)
// ---------------------------------------------------------------------------
__global__ void normalize_kernel(const float* __restrict__ in) {
    __shared__ float tile[Dc][33];
    __shared__ float psum[8][TN];
    __shared__ float sinv[TN];

    const int b      = blockIdx.y;
    const int n_base = blockIdx.x * TN;
    const int t      = threadIdx.x;

    const float4* src = (const float4*)(in + (size_t)b * Dc * Nc + n_base);

    float4 v[4];
    #pragma unroll
    for (int k = 0; k < 4; k++) {
        int f = t + 256 * k;
        int d = f >> 3;
        int q = f & 7;
        v[k] = src[(size_t)d * (Nc / 4) + q];
    }
    #pragma unroll
    for (int k = 0; k < 4; k++) {
        int f = t + 256 * k;
        int d = f >> 3;
        int n0 = (f & 7) * 4;
        tile[d][n0]     = v[k].x;
        tile[d][n0 + 1] = v[k].y;
        tile[d][n0 + 2] = v[k].z;
        tile[d][n0 + 3] = v[k].w;
    }
    __syncthreads();

    {
        int n0 = t & 31, c = t >> 5;
        float s = 0.f;
        #pragma unroll
        for (int dd = 0; dd < 16; dd++) {
            float x = tile[c * 16 + dd][n0];
            s += x * x;
        }
        psum[c][n0] = s;
    }
    __syncthreads();

    if (t < TN) {
        float s = 0.f;
        #pragma unroll
        for (int c = 0; c < 8; c++) s += psum[c][t];
        sinv[t] = 1.0f / fmaxf(sqrtf(s), 1e-12f);   // matches F.normalize eps
    }
    __syncthreads();

    const int wid = t >> 5, lane = t & 31;
    #pragma unroll
    for (int n0i = 0; n0i < 4; n0i++) {
        int n0 = wid + 8 * n0i;
        float inv = sinv[n0];
        __half2* dst = ((__half2*)g_norm4) + ((size_t)(b * Nc + n_base + n0)) * 64;
        #pragma unroll
        for (int k = 0; k < 2; k++) {
            int d = 2 * (lane + 32 * k);
            float2 f2 = make_float2(tile[d][n0] * inv, tile[d + 1][n0] * inv);
            dst[lane + 32 * k] = __float22half2_rn(f2);
        }
    }
}

// ---------------------------------------------------------------------------
// Kernel 2: quad-per-dot gather. Work-item = one (pos or neg) pair; 4 lanes
// per item, each lane loads 64B (4 x uint4) of each vector -> 8 independent
// LDG.128 per thread, quad reduce = 2 shfls (vs 10 warp-wide before).
// 256-thread block handles 64 items; items [0,P) = pos, [P,2P) = neg.
// ---------------------------------------------------------------------------
__global__ void gather_kernel(const int* __restrict__ pb, const int* __restrict__ pi,
                              const int* __restrict__ pj, const int* __restrict__ nb,
                              const int* __restrict__ ni, const int* __restrict__ nj,
                              int P) {
    const int t    = threadIdx.x;
    const int lane = t & 31;
    const int ql   = lane & 3;
    const int item = blockIdx.x * 64 + (t >> 2);

    float val = 0.f;
    if (item < 2 * P) {
        const bool neg = (item >= P);
        const int p = neg ? item - P : item;
        const int b = neg ? nb[p] : pb[p];
        const int i = neg ? ni[p] : pi[p];
        const int j = neg ? nj[p] : pj[p];

        const uint4* vi = g_norm4 + ((size_t)(b * Nc + i)) * 16 + ql * 4;
        const uint4* vj = g_norm4 + ((size_t)(b * Nc + j)) * 16 + ql * 4;

        uint4 a[4], c[4];
        #pragma unroll
        for (int u = 0; u < 4; u++) a[u] = vi[u];
        #pragma unroll
        for (int u = 0; u < 4; u++) c[u] = vj[u];

        float dot = 0.f;
        #pragma unroll
        for (int u = 0; u < 4; u++) {
            const unsigned* pa = &a[u].x;
            const unsigned* pc = &c[u].x;
            #pragma unroll
            for (int e = 0; e < 4; e++) {
                float2 fa = __half22float2(*(const __half2*)&pa[e]);
                float2 fc = __half22float2(*(const __half2*)&pc[e]);
                dot += fa.x * fc.x + fa.y * fc.y;
            }
        }
        // quad reduction (lanes ql=0..3)
        dot += __shfl_xor_sync(0xffffffffu, dot, 1);
        dot += __shfl_xor_sync(0xffffffffu, dot, 2);

        if (ql == 0) {
            float s = dot * TEMP_INV;
            float x = neg ? s : -s;          // softplus(x) = -log_sigmoid(-x)
            val = fmaxf(x, 0.f) + log1pf(expf(-fabsf(x)));
        }
    }

    // Block reduction: 64 quad-leader values -> fixed-order tree (deterministic)
    __shared__ float sred[64];
    if (ql == 0) sred[t >> 2] = val;
    __syncthreads();
    if (t < 32) {
        float s = sred[t] + sred[t + 32];
        #pragma unroll
        for (int off = 16; off; off >>= 1)
            s += __shfl_xor_sync(0xffffffffu, s, off);
        if (t == 0) g_partial[blockIdx.x] = s;
    }
}

// ---------------------------------------------------------------------------
// Kernel 3: deterministic final reduction (fixed strided order + tree).
// ---------------------------------------------------------------------------
__global__ void finalize_kernel(int nblocks, int P, float* __restrict__ out) {
    __shared__ float sred[1024];
    float s = 0.f;
    for (int k = threadIdx.x; k < nblocks; k += 1024) s += g_partial[k];
    sred[threadIdx.x] = s;
    __syncthreads();
    #pragma unroll
    for (int stride = 512; stride; stride >>= 1) {
        if (threadIdx.x < stride) sred[threadIdx.x] += sred[threadIdx.x + stride];
        __syncthreads();
    }
    if (threadIdx.x == 0) out[0] = sred[0] / (float)P;
}

extern "C" void kernel_launch(void* const* d_in, const int* in_sizes, int n_in,
                              void* d_out, int out_size) {
    const float* feats = (const float*)d_in[0];
    const int*   pb    = (const int*)d_in[1];
    const int*   pi    = (const int*)d_in[2];
    const int*   pj    = (const int*)d_in[3];
    const int*   nb    = (const int*)d_in[4];
    const int*   ni    = (const int*)d_in[5];
    const int*   nj    = (const int*)d_in[6];
    const int    P     = in_sizes[1];

    normalize_kernel<<<dim3(Nc / TN, Bc), 256>>>(feats);

    const int nblocks = (2 * P + 63) / 64;      // 64 items (quads) per block
    gather_kernel<<<nblocks, 256>>>(pb, pi, pj, nb, ni, nj, P);

    finalize_kernel<<<1, 1024>>>(nblocks, P, (float*)d_out);
}

// round 8
// speedup vs baseline: 1.6689x; 1.0970x over previous
#include <cuda_runtime.h>
#include <cuda_fp16.h>
#include <math.h>

// Problem shape (fixed by the dataset)
#define Bc 8
#define Dc 128
#define Nc 4096           // 64*64
#define TEMP_INV 10.0f    // 1 / 0.1
#define TN 32             // n-tile width in normalize

// Scratch (allocation-free rule: __device__ globals).
// Normalized features stored fp16, (B, N, D) with D contiguous: 256 B/vector.
__device__ uint4 g_norm4[Bc * Nc * Dc * 2 / 16];   // 8.4 MB, 16B-aligned
__device__ float g_partial[16384];                 // per-block partial loss sums

// ---------------------------------------------------------------------------
// Kernel 1: L2-normalize over D and transpose (B,D,N) -> (B,N,D), fp16 out.
// Single-barrier version: thread t = (r = t>>3, q = t&7) loads rows r+32k of
// columns 4q..4q+3 as float4, accumulates per-column sum-of-squares in
// REGISTERS, writes padded psum[32][33] + tile[128][33] (both conflict-free:
// bank = (r + 4q + c) mod 32 is bijective over the warp). After ONE barrier,
// each warp butterfly-reduces psum columns for the 4 vectors it writes.
// ---------------------------------------------------------------------------
__global__ void __launch_bounds__(256, 8) normalize_kernel(const float* __restrict__ in) {
    __shared__ float tile[Dc][33];
    __shared__ float psum[32][33];

    const int b      = blockIdx.y;
    const int n_base = blockIdx.x * TN;
    const int t      = threadIdx.x;
    const int r      = t >> 3;
    const int q      = t & 7;

    const float4* src = (const float4*)(in + (size_t)b * Dc * Nc + n_base);

    float4 v[4];
    #pragma unroll
    for (int k = 0; k < 4; k++)
        v[k] = src[(size_t)(r + 32 * k) * (Nc / 4) + q];

    // Register partial sums for the 4 owned columns over the 4 owned rows
    float s0 = 0.f, s1 = 0.f, s2 = 0.f, s3 = 0.f;
    #pragma unroll
    for (int k = 0; k < 4; k++) {
        s0 += v[k].x * v[k].x;
        s1 += v[k].y * v[k].y;
        s2 += v[k].z * v[k].z;
        s3 += v[k].w * v[k].w;
    }
    psum[r][4 * q + 0] = s0;
    psum[r][4 * q + 1] = s1;
    psum[r][4 * q + 2] = s2;
    psum[r][4 * q + 3] = s3;

    #pragma unroll
    for (int k = 0; k < 4; k++) {
        tile[r + 32 * k][4 * q + 0] = v[k].x;
        tile[r + 32 * k][4 * q + 1] = v[k].y;
        tile[r + 32 * k][4 * q + 2] = v[k].z;
        tile[r + 32 * k][4 * q + 3] = v[k].w;
    }
    __syncthreads();

    // Write phase: warp w writes vectors n0 = w + 8i. sinv computed per-warp
    // via butterfly (no second barrier needed).
    const int wid = t >> 5, lane = t & 31;
    #pragma unroll
    for (int i = 0; i < 4; i++) {
        const int n0 = wid + 8 * i;
        float sv = psum[lane][n0];
        #pragma unroll
        for (int off = 16; off; off >>= 1)
            sv += __shfl_xor_sync(0xffffffffu, sv, off);
        const float inv = 1.0f / fmaxf(sqrtf(sv), 1e-12f);  // F.normalize eps

        __half2* dst = ((__half2*)g_norm4) + ((size_t)(b * Nc + n_base + n0)) * 64;
        #pragma unroll
        for (int k = 0; k < 2; k++) {
            int d = 2 * (lane + 32 * k);
            float2 f2 = make_float2(tile[d][n0] * inv, tile[d + 1][n0] * inv);
            dst[lane + 32 * k] = __float22half2_rn(f2);
        }
    }
}

// ---------------------------------------------------------------------------
// Kernel 2: octet-per-dot gather. 8 lanes own one (pos or neg) pair; lane ol
// loads vi[ol], vi[ol+8], vj[ol], vj[ol+8] (each warp-instruction = 4 octets
// x one contiguous 128B line = 4 wavefronts -> 4 wf/dot, the floor).
// Octet reduce = 3 shfls. 256-thread block = 32 items.
// ---------------------------------------------------------------------------
__global__ void gather_kernel(const int* __restrict__ pb, const int* __restrict__ pi,
                              const int* __restrict__ pj, const int* __restrict__ nb,
                              const int* __restrict__ ni, const int* __restrict__ nj,
                              int P) {
    const int t    = threadIdx.x;
    const int ol   = t & 7;                      // lane within octet
    const int item = blockIdx.x * 32 + (t >> 3); // global octet = item index

    float val = 0.f;
    if (item < 2 * P) {
        const bool neg = (item >= P);
        const int p = neg ? item - P : item;
        const int b = neg ? nb[p] : pb[p];
        const int i = neg ? ni[p] : pi[p];
        const int j = neg ? nj[p] : pj[p];

        const uint4* vi = g_norm4 + ((size_t)(b * Nc + i)) * 16;
        const uint4* vj = g_norm4 + ((size_t)(b * Nc + j)) * 16;

        uint4 a0 = vi[ol];
        uint4 a1 = vi[ol + 8];
        uint4 c0 = vj[ol];
        uint4 c1 = vj[ol + 8];

        float dot = 0.f;
        const unsigned* pa0 = &a0.x; const unsigned* pc0 = &c0.x;
        const unsigned* pa1 = &a1.x; const unsigned* pc1 = &c1.x;
        #pragma unroll
        for (int e = 0; e < 4; e++) {
            float2 fa = __half22float2(*(const __half2*)&pa0[e]);
            float2 fc = __half22float2(*(const __half2*)&pc0[e]);
            dot += fa.x * fc.x + fa.y * fc.y;
            float2 ga = __half22float2(*(const __half2*)&pa1[e]);
            float2 gc = __half22float2(*(const __half2*)&pc1[e]);
            dot += ga.x * gc.x + ga.y * gc.y;
        }
        // octet reduction
        dot += __shfl_xor_sync(0xffffffffu, dot, 1);
        dot += __shfl_xor_sync(0xffffffffu, dot, 2);
        dot += __shfl_xor_sync(0xffffffffu, dot, 4);

        if (ol == 0) {
            float s = dot * TEMP_INV;
            float x = neg ? s : -s;          // softplus(x) = -log_sigmoid(-x)
            val = fmaxf(x, 0.f) + log1pf(expf(-fabsf(x)));
        }
    }

    // Block reduction: 32 octet-leader values -> fixed-order tree
    __shared__ float sred[32];
    if (ol == 0) sred[t >> 3] = val;
    __syncthreads();
    if (t < 32) {
        float s = sred[t];
        #pragma unroll
        for (int off = 16; off; off >>= 1)
            s += __shfl_xor_sync(0xffffffffu, s, off);
        if (t == 0) g_partial[blockIdx.x] = s;
    }
}

// ---------------------------------------------------------------------------
// Kernel 3: deterministic final reduction (fixed strided order + tree).
// ---------------------------------------------------------------------------
__global__ void finalize_kernel(int nblocks, int P, float* __restrict__ out) {
    __shared__ float sred[1024];
    float s = 0.f;
    for (int k = threadIdx.x; k < nblocks; k += 1024) s += g_partial[k];
    sred[threadIdx.x] = s;
    __syncthreads();
    #pragma unroll
    for (int stride = 512; stride; stride >>= 1) {
        if (threadIdx.x < stride) sred[threadIdx.x] += sred[threadIdx.x + stride];
        __syncthreads();
    }
    if (threadIdx.x == 0) out[0] = sred[0] / (float)P;
}

extern "C" void kernel_launch(void* const* d_in, const int* in_sizes, int n_in,
                              void* d_out, int out_size) {
    const float* feats = (const float*)d_in[0];
    const int*   pb    = (const int*)d_in[1];
    const int*   pi    = (const int*)d_in[2];
    const int*   pj    = (const int*)d_in[3];
    const int*   nb    = (const int*)d_in[4];
    const int*   ni    = (const int*)d_in[5];
    const int*   nj    = (const int*)d_in[6];
    const int    P     = in_sizes[1];

    normalize_kernel<<<dim3(Nc / TN, Bc), 256>>>(feats);

    const int nblocks = (2 * P + 31) / 32;      // 32 items (octets) per block
    gather_kernel<<<nblocks, 256>>>(pb, pi, pj, nb, ni, nj, P);

    finalize_kernel<<<1, 1024>>>(nblocks, P, (float*)d_out);
}

// round 9
// speedup vs baseline: 1.8902x; 1.1326x over previous
#include <cuda_runtime.h>
#include <cuda_fp16.h>
#include <cuda_fp8.h>
#include <math.h>

// Problem shape (fixed by the dataset)
#define Bc 8
#define Dc 128
#define Nc 4096           // 64*64
#define TEMP_INV 10.0f    // 1 / 0.1
#define TN 32             // n-tile width in normalize

// Scratch (allocation-free rule: __device__ globals).
// Normalized features stored fp8 e4m3, permuted-d packing:
// vector v (0..Bc*Nc-1) = 32 u32 words (128B); word L holds fp8 of
// d = L, L+32 (low half2) and d = L+64, L+96 (high half2).
// The SAME permutation applies to both operands of every dot, so the
// dot product is unchanged.
__device__ unsigned g_fp8[Bc * Nc * 32];           // 4.2 MB
__device__ float g_partial[16384];                 // per-block partial loss sums

// ---------------------------------------------------------------------------
// Kernel 1: L2-normalize over D and transpose (B,D,N) -> (B,N,D), fp8 out.
// Load/reduce phases identical to round-8 (register sumsq + single barrier).
// Write phase: lane L handles d = L+32k (conflict-free LDS: bank = L+n0),
// converts to 2x e4m3x2, packs one u32, one coalesced STG.32 per vector.
// ---------------------------------------------------------------------------
__global__ void __launch_bounds__(256, 8) normalize_kernel(const float* __restrict__ in) {
    __shared__ float tile[Dc][33];
    __shared__ float psum[32][33];

    const int b      = blockIdx.y;
    const int n_base = blockIdx.x * TN;
    const int t      = threadIdx.x;
    const int r      = t >> 3;
    const int q      = t & 7;

    const float4* src = (const float4*)(in + (size_t)b * Dc * Nc + n_base);

    float4 v[4];
    #pragma unroll
    for (int k = 0; k < 4; k++)
        v[k] = src[(size_t)(r + 32 * k) * (Nc / 4) + q];

    // Register partial sums for the 4 owned columns over the 4 owned rows
    float s0 = 0.f, s1 = 0.f, s2 = 0.f, s3 = 0.f;
    #pragma unroll
    for (int k = 0; k < 4; k++) {
        s0 += v[k].x * v[k].x;
        s1 += v[k].y * v[k].y;
        s2 += v[k].z * v[k].z;
        s3 += v[k].w * v[k].w;
    }
    psum[r][4 * q + 0] = s0;
    psum[r][4 * q + 1] = s1;
    psum[r][4 * q + 2] = s2;
    psum[r][4 * q + 3] = s3;

    #pragma unroll
    for (int k = 0; k < 4; k++) {
        tile[r + 32 * k][4 * q + 0] = v[k].x;
        tile[r + 32 * k][4 * q + 1] = v[k].y;
        tile[r + 32 * k][4 * q + 2] = v[k].z;
        tile[r + 32 * k][4 * q + 3] = v[k].w;
    }
    __syncthreads();

    // Write phase: warp w writes vectors n0 = w + 8i; sinv via 5-shfl butterfly.
    const int wid = t >> 5, lane = t & 31;
    #pragma unroll
    for (int i = 0; i < 4; i++) {
        const int n0 = wid + 8 * i;
        float sv = psum[lane][n0];
        #pragma unroll
        for (int off = 16; off; off >>= 1)
            sv += __shfl_xor_sync(0xffffffffu, sv, off);
        const float inv = 1.0f / fmaxf(sqrtf(sv), 1e-12f);  // F.normalize eps

        // lane owns d = lane + 32k (conflict-free: bank = lane + n0)
        float d0 = tile[lane][n0]      * inv;
        float d1 = tile[lane + 32][n0] * inv;
        float d2 = tile[lane + 64][n0] * inv;
        float d3 = tile[lane + 96][n0] * inv;

        __nv_fp8x2_storage_t lo =
            __nv_cvt_float2_to_fp8x2(make_float2(d0, d1), __NV_SATFINITE, __NV_E4M3);
        __nv_fp8x2_storage_t hi =
            __nv_cvt_float2_to_fp8x2(make_float2(d2, d3), __NV_SATFINITE, __NV_E4M3);
        unsigned w32 = (unsigned)lo | ((unsigned)hi << 16);

        g_fp8[((size_t)(b * Nc + n_base + n0)) * 32 + lane] = w32;
    }
}

// ---------------------------------------------------------------------------
// Kernel 2: octet-per-dot fp8 gather. 8 lanes own one pair; lane ol loads ONE
// uint4 (16 fp8) of each 128B vector -> per warp-instruction 4 octets x 1
// full line = 4 wf, 2 wf/dot total. e4m3x2->half2 cvt + HFMA2 accumulate,
// fp32 octet reduce (3 shfls). 512-thread block = 64 items.
// ---------------------------------------------------------------------------
__global__ void gather_kernel(const int* __restrict__ pb, const int* __restrict__ pi,
                              const int* __restrict__ pj, const int* __restrict__ nb,
                              const int* __restrict__ ni, const int* __restrict__ nj,
                              int P) {
    const int t    = threadIdx.x;
    const int ol   = t & 7;                      // lane within octet
    const int item = blockIdx.x * 64 + (t >> 3); // global octet = item index

    float val = 0.f;
    if (item < 2 * P) {
        const bool neg = (item >= P);
        const int p = neg ? item - P : item;
        const int b = neg ? nb[p] : pb[p];
        const int i = neg ? ni[p] : pi[p];
        const int j = neg ? nj[p] : pj[p];

        const uint4* vi = (const uint4*)g_fp8 + ((size_t)(b * Nc + i)) * 8;
        const uint4* vj = (const uint4*)g_fp8 + ((size_t)(b * Nc + j)) * 8;

        uint4 a = vi[ol];
        uint4 c = vj[ol];

        __half2 acc = __float2half2_rn(0.f);
        const unsigned* pa = &a.x;
        const unsigned* pc = &c.x;
        #pragma unroll
        for (int m = 0; m < 4; m++) {
            __half2 alo = __half2(__nv_cvt_fp8x2_to_halfraw2(
                (__nv_fp8x2_storage_t)(pa[m] & 0xffffu), __NV_E4M3));
            __half2 clo = __half2(__nv_cvt_fp8x2_to_halfraw2(
                (__nv_fp8x2_storage_t)(pc[m] & 0xffffu), __NV_E4M3));
            acc = __hfma2(alo, clo, acc);
            __half2 ahi = __half2(__nv_cvt_fp8x2_to_halfraw2(
                (__nv_fp8x2_storage_t)(pa[m] >> 16), __NV_E4M3));
            __half2 chi = __half2(__nv_cvt_fp8x2_to_halfraw2(
                (__nv_fp8x2_storage_t)(pc[m] >> 16), __NV_E4M3));
            acc = __hfma2(ahi, chi, acc);
        }
        float2 f = __half22float2(acc);
        float dot = f.x + f.y;

        // octet reduction
        dot += __shfl_xor_sync(0xffffffffu, dot, 1);
        dot += __shfl_xor_sync(0xffffffffu, dot, 2);
        dot += __shfl_xor_sync(0xffffffffu, dot, 4);

        if (ol == 0) {
            float s = dot * TEMP_INV;
            float x = neg ? s : -s;          // softplus(x) = -log_sigmoid(-x)
            val = fmaxf(x, 0.f) + log1pf(expf(-fabsf(x)));
        }
    }

    // Block reduction: 64 octet-leader values -> fixed-order tree
    __shared__ float sred[64];
    if (ol == 0) sred[t >> 3] = val;
    __syncthreads();
    if (t < 32) {
        float s = sred[t] + sred[t + 32];
        #pragma unroll
        for (int off = 16; off; off >>= 1)
            s += __shfl_xor_sync(0xffffffffu, s, off);
        if (t == 0) g_partial[blockIdx.x] = s;
    }
}

// ---------------------------------------------------------------------------
// Kernel 3: deterministic final reduction (fixed strided order + tree).
// ---------------------------------------------------------------------------
__global__ void finalize_kernel(int nblocks, int P, float* __restrict__ out) {
    __shared__ float sred[1024];
    float s = 0.f;
    for (int k = threadIdx.x; k < nblocks; k += 1024) s += g_partial[k];
    sred[threadIdx.x] = s;
    __syncthreads();
    #pragma unroll
    for (int stride = 512; stride; stride >>= 1) {
        if (threadIdx.x < stride) sred[threadIdx.x] += sred[threadIdx.x + stride];
        __syncthreads();
    }
    if (threadIdx.x == 0) out[0] = sred[0] / (float)P;
}

extern "C" void kernel_launch(void* const* d_in, const int* in_sizes, int n_in,
                              void* d_out, int out_size) {
    const float* feats = (const float*)d_in[0];
    const int*   pb    = (const int*)d_in[1];
    const int*   pi    = (const int*)d_in[2];
    const int*   pj    = (const int*)d_in[3];
    const int*   nb    = (const int*)d_in[4];
    const int*   ni    = (const int*)d_in[5];
    const int*   nj    = (const int*)d_in[6];
    const int    P     = in_sizes[1];

    normalize_kernel<<<dim3(Nc / TN, Bc), 256>>>(feats);

    const int nblocks = (2 * P + 63) / 64;      // 64 items (octets) per block
    gather_kernel<<<nblocks, 512>>>(pb, pi, pj, nb, ni, nj, P);

    finalize_kernel<<<1, 1024>>>(nblocks, P, (float*)d_out);
}